// round 8
// baseline (speedup 1.0000x reference)
#include <cuda_runtime.h>
#include <cuda_bf16.h>
#include <cstdint>

#define NROWS 65536
#define CCLS  1024
#define DDIM  512

// ---------------- device scratch (allocation-free rule) ----------------
__device__ __nv_bfloat16 g_fhi[(size_t)NROWS * DDIM];   // 64 MB
__device__ __nv_bfloat16 g_flo[(size_t)NROWS * DDIM];   // 64 MB
__device__ __nv_bfloat16 g_phi[CCLS * DDIM];
__device__ __nv_bfloat16 g_plo[CCLS * DDIM];
__device__ float g_sums[CCLS * DDIM];
__device__ float g_cnt[CCLS];
__device__ int   g_lab64;

// ---------------- label dtype sniff ----------------
__global__ void detect_labels_kernel(const unsigned int* __restrict__ lab) {
    __shared__ int any_nz;
    if (threadIdx.x == 0) any_nz = 0;
    __syncthreads();
    int local = 0;
    for (int i = threadIdx.x; i < 8192; i += blockDim.x)
        if (lab[2 * i + 1] != 0u) local = 1;
    if (local) any_nz = 1;
    __syncthreads();
    if (threadIdx.x == 0) g_lab64 = any_nz ? 0 : 1;
}

__global__ void zero_kernel() {
    int i = blockIdx.x * blockDim.x + threadIdx.x;
    if (i < CCLS * DDIM) g_sums[i] = 0.0f;
    if (i < CCLS)        g_cnt[i]  = 0.0f;
}

// ---------------- normalize + scatter + bf16 split ----------------
__global__ __launch_bounds__(256) void norm_scatter_kernel(
    const float* __restrict__ feats, const void* __restrict__ labels)
{
    int row  = (blockIdx.x * blockDim.x + threadIdx.x) >> 5;
    int lane = threadIdx.x & 31;
    if (row >= NROWS) return;

    const float4* src = (const float4*)(feats + (size_t)row * DDIM);
    float4 v[4];
    float ss = 0.0f;
#pragma unroll
    for (int j = 0; j < 4; j++) {
        v[j] = src[lane + 32 * j];
        ss += v[j].x * v[j].x + v[j].y * v[j].y + v[j].z * v[j].z + v[j].w * v[j].w;
    }
#pragma unroll
    for (int o = 16; o; o >>= 1) ss += __shfl_xor_sync(0xFFFFFFFFu, ss, o);
    float inv = 1.0f / fmaxf(sqrtf(ss), 1e-12f);

    int lab;
    if (g_lab64) lab = (int)((const long long*)labels)[row];
    else         lab = ((const int*)labels)[row];

    float* sumrow = g_sums + (size_t)lab * DDIM;
    __nv_bfloat16* hrow = g_fhi + (size_t)row * DDIM;
    __nv_bfloat16* lrow = g_flo + (size_t)row * DDIM;

#pragma unroll
    for (int j = 0; j < 4; j++) {
        float4 w = make_float4(v[j].x * inv, v[j].y * inv, v[j].z * inv, v[j].w * inv);
        int base = (lane + 32 * j) * 4;
        asm volatile("red.global.add.v4.f32 [%0], {%1,%2,%3,%4};"
                     :: "l"(sumrow + base), "f"(w.x), "f"(w.y), "f"(w.z), "f"(w.w) : "memory");
        __nv_bfloat162 h0 = __floats2bfloat162_rn(w.x, w.y);
        __nv_bfloat162 h1 = __floats2bfloat162_rn(w.z, w.w);
        float rx = w.x - __bfloat162float(h0.x);
        float ry = w.y - __bfloat162float(h0.y);
        float rz = w.z - __bfloat162float(h1.x);
        float rw = w.w - __bfloat162float(h1.y);
        __nv_bfloat162 l0 = __floats2bfloat162_rn(rx, ry);
        __nv_bfloat162 l1 = __floats2bfloat162_rn(rz, rw);
        uint2 hv, lv;
        hv.x = *(unsigned*)&h0; hv.y = *(unsigned*)&h1;
        lv.x = *(unsigned*)&l0; lv.y = *(unsigned*)&l1;
        *(uint2*)(hrow + base) = hv;
        *(uint2*)(lrow + base) = lv;
    }
    if (lane == 0) atomicAdd(&g_cnt[lab], 1.0f);
}

// ---------------- prototype EMA update + renorm + bf16 split ----------------
__global__ __launch_bounds__(128) void proto_update_kernel(
    const float* __restrict__ protos)
{
    int c = blockIdx.x;
    int t = threadIdx.x;
    float cnt = g_cnt[c];

    float4 pv = ((const float4*)(protos + (size_t)c * DDIM))[t];
    float4 sv = ((const float4*)(g_sums + (size_t)c * DDIM))[t];

    float ic = 1.0f / fmaxf(cnt, 1.0f);
    float4 e = make_float4(0.9f * pv.x + 0.1f * sv.x * ic,
                           0.9f * pv.y + 0.1f * sv.y * ic,
                           0.9f * pv.z + 0.1f * sv.z * ic,
                           0.9f * pv.w + 0.1f * sv.w * ic);

    float ss = e.x * e.x + e.y * e.y + e.z * e.z + e.w * e.w;
#pragma unroll
    for (int o = 16; o; o >>= 1) ss += __shfl_xor_sync(0xFFFFFFFFu, ss, o);
    __shared__ float red[4];
    if ((t & 31) == 0) red[t >> 5] = ss;
    __syncthreads();
    float tot = red[0] + red[1] + red[2] + red[3];
    float inv = 1.0f / fmaxf(sqrtf(tot), 1e-12f);

    float4 out;
    if (cnt > 0.0f)
        out = make_float4(e.x * inv, e.y * inv, e.z * inv, e.w * inv);
    else
        out = pv;

    int base = t * 4;
    __nv_bfloat162 h0 = __floats2bfloat162_rn(out.x, out.y);
    __nv_bfloat162 h1 = __floats2bfloat162_rn(out.z, out.w);
    float rx = out.x - __bfloat162float(h0.x);
    float ry = out.y - __bfloat162float(h0.y);
    float rz = out.z - __bfloat162float(h1.x);
    float rw = out.w - __bfloat162float(h1.y);
    __nv_bfloat162 l0 = __floats2bfloat162_rn(rx, ry);
    __nv_bfloat162 l1 = __floats2bfloat162_rn(rz, rw);
    uint2 hv, lv;
    hv.x = *(unsigned*)&h0; hv.y = *(unsigned*)&h1;
    lv.x = *(unsigned*)&l0; lv.y = *(unsigned*)&l1;
    *(uint2*)(g_phi + (size_t)c * DDIM + base) = hv;
    *(uint2*)(g_plo + (size_t)c * DDIM + base) = lv;
}

// ---------------- persistent split-bf16 GEMM via ldmatrix + mma.sync ----------------
// C = Ahi*BhiT + Ahi*BloT + Alo*BhiT  (fp32 accum)
#define BM 128
#define BN 128
#define BK 64
#define KCHUNKS (DDIM / BK)        // 8 per tile
#define NTILES ((NROWS / BM) * (CCLS / BN))   // 4096
#define GRIDX 148
#define LDS_EL 72                  // smem row stride in bf16 elems (144 B)
#define TILE_B (128 * LDS_EL * 2)  // 18432
#define STAGE_B (4 * TILE_B)       // 73728
#define STAGES 3
#define SMEM_GEMM (STAGES * STAGE_B)   // 221184

__device__ __forceinline__ uint32_t smem_u32(const void* p) {
    uint32_t a;
    asm("{ .reg .u64 t; cvta.to.shared.u64 t, %1; cvt.u32.u64 %0, t; }" : "=r"(a) : "l"(p));
    return a;
}
__device__ __forceinline__ void cp16(uint32_t sm, const void* gm) {
    asm volatile("cp.async.cg.shared.global [%0], [%1], 16;" :: "r"(sm), "l"(gm));
}
__device__ __forceinline__ void ldsm_x4(uint32_t* r, uint32_t a) {
    asm volatile("ldmatrix.sync.aligned.m8n8.x4.shared.b16 {%0,%1,%2,%3}, [%4];"
                 : "=r"(r[0]), "=r"(r[1]), "=r"(r[2]), "=r"(r[3]) : "r"(a));
}
__device__ __forceinline__ void mma16816(float* d, const uint32_t* a, const uint32_t* b) {
    asm volatile("mma.sync.aligned.m16n8k16.row.col.f32.bf16.bf16.f32 "
                 "{%0,%1,%2,%3}, {%4,%5,%6,%7}, {%8,%9}, {%0,%1,%2,%3};"
                 : "+f"(d[0]), "+f"(d[1]), "+f"(d[2]), "+f"(d[3])
                 : "r"(a[0]), "r"(a[1]), "r"(a[2]), "r"(b[0]), "r"(a[3]), "r"(b[1]));
}
// NOTE: operand order matters; keep canonical form below instead.
__device__ __forceinline__ void mma16816c(float* d, const uint32_t* a, const uint32_t* b) {
    asm volatile("mma.sync.aligned.m16n8k16.row.col.f32.bf16.bf16.f32 "
                 "{%0,%1,%2,%3}, {%4,%5,%6,%7}, {%8,%9}, {%0,%1,%2,%3};"
                 : "+f"(d[0]), "+f"(d[1]), "+f"(d[2]), "+f"(d[3])
                 : "r"(a[0]), "r"(a[1]), "r"(a[2]), "r"(a[3]), "r"(b[0]), "r"(b[1]));
}

// issue the 4-buffer loads of one (tile, chunk) into a stage
__device__ __forceinline__ void load_chunk(uint32_t stb, int tile, int c, int tid) {
    const int m0 = (tile >> 3) * BM;
    const int n0 = (tile & 7) * BN;
    const __nv_bfloat16* bases[4] = {
        g_fhi + (size_t)m0 * DDIM, g_flo + (size_t)m0 * DDIM,
        g_phi + (size_t)n0 * DDIM, g_plo + (size_t)n0 * DDIM };
    const int r8 = tid >> 3, kc = tid & 7;
    const int kg = c * BK + kc * 8;
#pragma unroll
    for (int buf = 0; buf < 4; buf++) {
#pragma unroll
        for (int b = 0; b < 4; b++) {
            int r = b * 32 + r8;
            cp16(stb + buf * TILE_B + r * (LDS_EL * 2) + kc * 16,
                 bases[buf] + (size_t)r * DDIM + kg);
        }
    }
}

__global__ __launch_bounds__(256, 1) void gemm_kernel(float* __restrict__ Cout)
{
    extern __shared__ char smem[];
    const uint32_t sb = smem_u32(smem);
    const int tid  = threadIdx.x;
    const int lane = tid & 31;
    const int wid  = tid >> 5;
    const int mwarp = wid >> 1;          // 0..3
    const int nwarp = wid & 1;           // 0..1

    // ldmatrix lane addressing (both operands [row][k], k contiguous -> non-trans)
    const int a_lr = lane & 15, a_lc = lane >> 4;
    const int b_q = lane >> 3;
    const int b_n = ((b_q >> 1) << 3) + (lane & 7);
    const int b_k8 = (b_q & 1) << 3;

    // producer iterator (runs STAGES-1 chunks ahead, across tile boundaries)
    int prod_tile = blockIdx.x, prod_c = 0;

    // prologue: fill 2 stages
#pragma unroll
    for (int s = 0; s < 2; s++) {
        if (prod_tile < NTILES) load_chunk(sb + s * STAGE_B, prod_tile, prod_c, tid);
        asm volatile("cp.async.commit_group;" ::: "memory");
        if (++prod_c == KCHUNKS) { prod_c = 0; prod_tile += GRIDX; }
    }

    int stage = 0;
    for (int tile = blockIdx.x; tile < NTILES; tile += GRIDX) {
        float acc[2][8][4];
#pragma unroll
        for (int mt = 0; mt < 2; mt++)
#pragma unroll
            for (int nt = 0; nt < 8; nt++)
#pragma unroll
                for (int q = 0; q < 4; q++) acc[mt][nt][q] = 0.0f;

        for (int c = 0; c < KCHUNKS; c++) {
            asm volatile("cp.async.wait_group 1;" ::: "memory");
            __syncthreads();

            // produce next chunk into the stage freed two iterations ago
            {
                int ps = stage + 2; if (ps >= STAGES) ps -= STAGES;
                if (prod_tile < NTILES) load_chunk(sb + ps * STAGE_B, prod_tile, prod_c, tid);
                asm volatile("cp.async.commit_group;" ::: "memory");  // always commit
                if (++prod_c == KCHUNKS) { prod_c = 0; prod_tile += GRIDX; }
            }

            const uint32_t stb = sb + stage * STAGE_B;
#pragma unroll
            for (int kk = 0; kk < BK; kk += 16) {
                uint32_t ah[2][4], al[2][4], bh[8][2], bl[8][2];
#pragma unroll
                for (int mt = 0; mt < 2; mt++) {
                    uint32_t ab = stb + (mwarp * 32 + mt * 16 + a_lr) * (LDS_EL * 2)
                                       + (kk + a_lc * 8) * 2;
                    ldsm_x4(ah[mt], ab + 0 * TILE_B);
                    ldsm_x4(al[mt], ab + 1 * TILE_B);
                }
#pragma unroll
                for (int np = 0; np < 4; np++) {
                    uint32_t bb = stb + (nwarp * 64 + np * 16 + b_n) * (LDS_EL * 2)
                                       + (kk + b_k8) * 2;
                    uint32_t rh[4], rl[4];
                    ldsm_x4(rh, bb + 2 * TILE_B);
                    ldsm_x4(rl, bb + 3 * TILE_B);
                    bh[2 * np][0] = rh[0]; bh[2 * np][1] = rh[1];
                    bh[2 * np + 1][0] = rh[2]; bh[2 * np + 1][1] = rh[3];
                    bl[2 * np][0] = rl[0]; bl[2 * np][1] = rl[1];
                    bl[2 * np + 1][0] = rl[2]; bl[2 * np + 1][1] = rl[3];
                }
#pragma unroll
                for (int mt = 0; mt < 2; mt++)
#pragma unroll
                    for (int nt = 0; nt < 8; nt++) {
                        mma16816c(acc[mt][nt], ah[mt], bh[nt]);
                        mma16816c(acc[mt][nt], ah[mt], bl[nt]);
                        mma16816c(acc[mt][nt], al[mt], bh[nt]);
                    }
            }
            stage = stage + 1; if (stage >= STAGES) stage -= STAGES;
        }

        // epilogue for this tile (registers only; pipeline keeps running)
        const int m0 = (tile >> 3) * BM;
        const int n0 = (tile & 7) * BN;
        const int rbase = m0 + mwarp * 32 + (lane >> 2);
        const int cbase = n0 + nwarp * 64 + (lane & 3) * 2;
#pragma unroll
        for (int mt = 0; mt < 2; mt++) {
            int r = rbase + mt * 16;
#pragma unroll
            for (int nt = 0; nt < 8; nt++) {
                int cc = cbase + nt * 8;
                *(float2*)(Cout + (size_t)r * CCLS + cc) =
                    make_float2(acc[mt][nt][0], acc[mt][nt][1]);
                *(float2*)(Cout + (size_t)(r + 8) * CCLS + cc) =
                    make_float2(acc[mt][nt][2], acc[mt][nt][3]);
            }
        }
    }
}

// ---------------- host launcher ----------------
extern "C" void kernel_launch(void* const* d_in, const int* in_sizes, int n_in,
                              void* d_out, int out_size)
{
    const float* feats  = (const float*)d_in[0];
    const float* protos = (const float*)d_in[1];
    const void*  labels = d_in[2];
    float* out = (float*)d_out;

    static bool attr_set = false;
    if (!attr_set) {
        cudaFuncSetAttribute(gemm_kernel,
                             cudaFuncAttributeMaxDynamicSharedMemorySize, SMEM_GEMM);
        attr_set = true;
    }

    detect_labels_kernel<<<1, 256>>>((const unsigned int*)labels);
    zero_kernel<<<(CCLS * DDIM + 255) / 256, 256>>>();
    norm_scatter_kernel<<<(NROWS * 32 + 255) / 256, 256>>>(feats, labels);
    proto_update_kernel<<<CCLS, 128>>>(protos);

    gemm_kernel<<<GRIDX, 256, SMEM_GEMM>>>(out);
}

// round 9
// speedup vs baseline: 1.3538x; 1.3538x over previous
#include <cuda_runtime.h>
#include <cuda_bf16.h>
#include <cstdint>

#define NROWS 65536
#define CCLS  1024
#define DDIM  512

// ---------------- device scratch (allocation-free rule) ----------------
__device__ __nv_bfloat16 g_fhi[(size_t)NROWS * DDIM];   // 64 MB
__device__ __nv_bfloat16 g_flo[(size_t)NROWS * DDIM];   // 64 MB
__device__ __nv_bfloat16 g_phi[CCLS * DDIM];
__device__ __nv_bfloat16 g_plo[CCLS * DDIM];
__device__ float g_sums[CCLS * DDIM];
__device__ float g_cnt[CCLS];
__device__ int   g_lab64;

// ---------------- label dtype sniff ----------------
__global__ void detect_labels_kernel(const unsigned int* __restrict__ lab) {
    __shared__ int any_nz;
    if (threadIdx.x == 0) any_nz = 0;
    __syncthreads();
    int local = 0;
    for (int i = threadIdx.x; i < 8192; i += blockDim.x)
        if (lab[2 * i + 1] != 0u) local = 1;
    if (local) any_nz = 1;
    __syncthreads();
    if (threadIdx.x == 0) g_lab64 = any_nz ? 0 : 1;
}

__global__ void zero_kernel() {
    int i = blockIdx.x * blockDim.x + threadIdx.x;
    if (i < CCLS * DDIM) g_sums[i] = 0.0f;
    if (i < CCLS)        g_cnt[i]  = 0.0f;
}

// ---------------- normalize + scatter + bf16 split ----------------
__global__ __launch_bounds__(256) void norm_scatter_kernel(
    const float* __restrict__ feats, const void* __restrict__ labels)
{
    int row  = (blockIdx.x * blockDim.x + threadIdx.x) >> 5;
    int lane = threadIdx.x & 31;
    if (row >= NROWS) return;

    const float4* src = (const float4*)(feats + (size_t)row * DDIM);
    float4 v[4];
    float ss = 0.0f;
#pragma unroll
    for (int j = 0; j < 4; j++) {
        v[j] = src[lane + 32 * j];
        ss += v[j].x * v[j].x + v[j].y * v[j].y + v[j].z * v[j].z + v[j].w * v[j].w;
    }
#pragma unroll
    for (int o = 16; o; o >>= 1) ss += __shfl_xor_sync(0xFFFFFFFFu, ss, o);
    float inv = 1.0f / fmaxf(sqrtf(ss), 1e-12f);

    int lab;
    if (g_lab64) lab = (int)((const long long*)labels)[row];
    else         lab = ((const int*)labels)[row];

    float* sumrow = g_sums + (size_t)lab * DDIM;
    __nv_bfloat16* hrow = g_fhi + (size_t)row * DDIM;
    __nv_bfloat16* lrow = g_flo + (size_t)row * DDIM;

#pragma unroll
    for (int j = 0; j < 4; j++) {
        float4 w = make_float4(v[j].x * inv, v[j].y * inv, v[j].z * inv, v[j].w * inv);
        int base = (lane + 32 * j) * 4;
        asm volatile("red.global.add.v4.f32 [%0], {%1,%2,%3,%4};"
                     :: "l"(sumrow + base), "f"(w.x), "f"(w.y), "f"(w.z), "f"(w.w) : "memory");
        __nv_bfloat162 h0 = __floats2bfloat162_rn(w.x, w.y);
        __nv_bfloat162 h1 = __floats2bfloat162_rn(w.z, w.w);
        float rx = w.x - __bfloat162float(h0.x);
        float ry = w.y - __bfloat162float(h0.y);
        float rz = w.z - __bfloat162float(h1.x);
        float rw = w.w - __bfloat162float(h1.y);
        __nv_bfloat162 l0 = __floats2bfloat162_rn(rx, ry);
        __nv_bfloat162 l1 = __floats2bfloat162_rn(rz, rw);
        uint2 hv, lv;
        hv.x = *(unsigned*)&h0; hv.y = *(unsigned*)&h1;
        lv.x = *(unsigned*)&l0; lv.y = *(unsigned*)&l1;
        *(uint2*)(hrow + base) = hv;
        *(uint2*)(lrow + base) = lv;
    }
    if (lane == 0) atomicAdd(&g_cnt[lab], 1.0f);
}

// ---------------- prototype EMA update + renorm + bf16 split ----------------
__global__ __launch_bounds__(128) void proto_update_kernel(
    const float* __restrict__ protos)
{
    int c = blockIdx.x;
    int t = threadIdx.x;
    float cnt = g_cnt[c];

    float4 pv = ((const float4*)(protos + (size_t)c * DDIM))[t];
    float4 sv = ((const float4*)(g_sums + (size_t)c * DDIM))[t];

    float ic = 1.0f / fmaxf(cnt, 1.0f);
    float4 e = make_float4(0.9f * pv.x + 0.1f * sv.x * ic,
                           0.9f * pv.y + 0.1f * sv.y * ic,
                           0.9f * pv.z + 0.1f * sv.z * ic,
                           0.9f * pv.w + 0.1f * sv.w * ic);

    float ss = e.x * e.x + e.y * e.y + e.z * e.z + e.w * e.w;
#pragma unroll
    for (int o = 16; o; o >>= 1) ss += __shfl_xor_sync(0xFFFFFFFFu, ss, o);
    __shared__ float red[4];
    if ((t & 31) == 0) red[t >> 5] = ss;
    __syncthreads();
    float tot = red[0] + red[1] + red[2] + red[3];
    float inv = 1.0f / fmaxf(sqrtf(tot), 1e-12f);

    float4 out;
    if (cnt > 0.0f)
        out = make_float4(e.x * inv, e.y * inv, e.z * inv, e.w * inv);
    else
        out = pv;

    int base = t * 4;
    __nv_bfloat162 h0 = __floats2bfloat162_rn(out.x, out.y);
    __nv_bfloat162 h1 = __floats2bfloat162_rn(out.z, out.w);
    float rx = out.x - __bfloat162float(h0.x);
    float ry = out.y - __bfloat162float(h0.y);
    float rz = out.z - __bfloat162float(h1.x);
    float rw = out.w - __bfloat162float(h1.y);
    __nv_bfloat162 l0 = __floats2bfloat162_rn(rx, ry);
    __nv_bfloat162 l1 = __floats2bfloat162_rn(rz, rw);
    uint2 hv, lv;
    hv.x = *(unsigned*)&h0; hv.y = *(unsigned*)&h1;
    lv.x = *(unsigned*)&l0; lv.y = *(unsigned*)&l1;
    *(uint2*)(g_phi + (size_t)c * DDIM + base) = hv;
    *(uint2*)(g_plo + (size_t)c * DDIM + base) = lv;
}

// ---------------- split-bf16 GEMM via ldmatrix + mma.sync ----------------
// C = Ahi*BhiT + Ahi*BloT + Alo*BhiT  (fp32 accum)
#define BM 128
#define BN 128
#define BK 32
#define NCHUNKS (DDIM / BK)       // 16
#define STAGES 5
#define PRO 4                      // prologue depth (stages filled up-front)
#define WG  3                      // wait_group bound (<= PRO-1)
#define LDS_EL 40                  // smem row stride in bf16 elems (80 B)
#define TILE_BYTES (128 * LDS_EL * 2)   // 10240
#define OFF_AHI 0
#define OFF_ALO (1 * TILE_BYTES)
#define OFF_BHI (2 * TILE_BYTES)
#define OFF_BLO (3 * TILE_BYTES)
#define STAGE_BYTES (4 * TILE_BYTES)    // 40960
#define SMEM_GEMM (STAGES * STAGE_BYTES) // 204800

__device__ __forceinline__ uint32_t smem_u32(const void* p) {
    uint32_t a;
    asm("{ .reg .u64 t; cvta.to.shared.u64 t, %1; cvt.u32.u64 %0, t; }" : "=r"(a) : "l"(p));
    return a;
}
__device__ __forceinline__ void cp16(uint32_t sm, const void* gm) {
    asm volatile("cp.async.cg.shared.global [%0], [%1], 16;" :: "r"(sm), "l"(gm));
}
__device__ __forceinline__ void ldsm_x4(uint32_t* r, uint32_t a) {
    asm volatile("ldmatrix.sync.aligned.m8n8.x4.shared.b16 {%0,%1,%2,%3}, [%4];"
                 : "=r"(r[0]), "=r"(r[1]), "=r"(r[2]), "=r"(r[3]) : "r"(a));
}
__device__ __forceinline__ void mma16816(float* d, const uint32_t* a, const uint32_t* b) {
    asm volatile("mma.sync.aligned.m16n8k16.row.col.f32.bf16.bf16.f32 "
                 "{%0,%1,%2,%3}, {%4,%5,%6,%7}, {%8,%9}, {%0,%1,%2,%3};"
                 : "+f"(d[0]), "+f"(d[1]), "+f"(d[2]), "+f"(d[3])
                 : "r"(a[0]), "r"(a[1]), "r"(a[2]), "r"(a[3]), "r"(b[0]), "r"(b[1]));
}

__global__ __launch_bounds__(256, 1) void gemm_kernel(float* __restrict__ Cout)
{
    extern __shared__ char smem[];
    const uint32_t sb = smem_u32(smem);
    const int tid  = threadIdx.x;
    const int lane = tid & 31;
    const int wid  = tid >> 5;
    const int mwarp = wid >> 1;          // 0..3
    const int nwarp = wid & 1;           // 0..1
    const int m0 = blockIdx.y * BM;
    const int n0 = blockIdx.x * BN;

    const __nv_bfloat16* srcs[4] = {
        g_fhi + (size_t)m0 * DDIM, g_flo + (size_t)m0 * DDIM,
        g_phi + (size_t)n0 * DDIM, g_plo + (size_t)n0 * DDIM };
    const int offs[4] = { OFF_AHI, OFF_ALO, OFF_BHI, OFF_BLO };

    const int r0c = tid >> 2, kc0 = tid & 3;

    float acc[2][8][4];
#pragma unroll
    for (int mt = 0; mt < 2; mt++)
#pragma unroll
        for (int nt = 0; nt < 8; nt++)
#pragma unroll
            for (int q = 0; q < 4; q++) acc[mt][nt][q] = 0.0f;

    // ---- prologue: fill PRO stages ----
#pragma unroll
    for (int s = 0; s < PRO; s++) {
        const int k0 = s * BK;
        const uint32_t stb = sb + s * STAGE_BYTES;
#pragma unroll
        for (int t = 0; t < 4; t++) {
#pragma unroll
            for (int i = 0; i < 2; i++) {
                int row = r0c + i * 64;
                cp16(stb + offs[t] + row * (LDS_EL * 2) + kc0 * 16,
                     srcs[t] + (size_t)row * DDIM + k0 + kc0 * 8);
            }
        }
        asm volatile("cp.async.commit_group;" ::: "memory");
    }

    // ldmatrix lane addressing (both operands [row][k], k contiguous -> non-trans)
    const int a_lr = lane & 15, a_lc = lane >> 4;
    const int b_q = lane >> 3;
    const int b_n = ((b_q >> 1) << 3) + (lane & 7);
    const int b_k8 = (b_q & 1) << 3;

    for (int c = 0; c < NCHUNKS; c++) {
        // commits so far = PRO + c; waiting to <=WG pending retires chunks 0..c
        asm volatile("cp.async.wait_group %0;" :: "n"(WG) : "memory");
        __syncthreads();

        // produce chunk c+PRO into the stage consumed at iteration c-1
        {
            const int cn = c + PRO;
            if (cn < NCHUNKS) {
                const int k0 = cn * BK;
                const uint32_t stb = sb + (cn % STAGES) * STAGE_BYTES;
#pragma unroll
                for (int t = 0; t < 4; t++) {
#pragma unroll
                    for (int i = 0; i < 2; i++) {
                        int row = r0c + i * 64;
                        cp16(stb + offs[t] + row * (LDS_EL * 2) + kc0 * 16,
                             srcs[t] + (size_t)row * DDIM + k0 + kc0 * 8);
                    }
                }
            }
            asm volatile("cp.async.commit_group;" ::: "memory");  // ALWAYS commit
        }

        const uint32_t stb = sb + (c % STAGES) * STAGE_BYTES;
#pragma unroll
        for (int kk = 0; kk < BK; kk += 16) {
            uint32_t ah[2][4], al[2][4], bh[8][2], bl[8][2];
#pragma unroll
            for (int mt = 0; mt < 2; mt++) {
                uint32_t ab = stb + (mwarp * 32 + mt * 16 + a_lr) * (LDS_EL * 2)
                                   + (kk + a_lc * 8) * 2;
                ldsm_x4(ah[mt], ab + OFF_AHI);
                ldsm_x4(al[mt], ab + OFF_ALO);
            }
#pragma unroll
            for (int np = 0; np < 4; np++) {
                uint32_t bb = stb + (nwarp * 64 + np * 16 + b_n) * (LDS_EL * 2)
                                   + (kk + b_k8) * 2;
                uint32_t rh[4], rl[4];
                ldsm_x4(rh, bb + OFF_BHI);
                ldsm_x4(rl, bb + OFF_BLO);
                bh[2 * np][0] = rh[0]; bh[2 * np][1] = rh[1];
                bh[2 * np + 1][0] = rh[2]; bh[2 * np + 1][1] = rh[3];
                bl[2 * np][0] = rl[0]; bl[2 * np][1] = rl[1];
                bl[2 * np + 1][0] = rl[2]; bl[2 * np + 1][1] = rl[3];
            }
#pragma unroll
            for (int mt = 0; mt < 2; mt++)
#pragma unroll
                for (int nt = 0; nt < 8; nt++) {
                    mma16816(acc[mt][nt], ah[mt], bh[nt]);
                    mma16816(acc[mt][nt], ah[mt], bl[nt]);
                    mma16816(acc[mt][nt], al[mt], bh[nt]);
                }
        }
    }

    // ---- epilogue: direct fp32 stores ----
    const int rbase = m0 + mwarp * 32 + (lane >> 2);
    const int cbase = n0 + nwarp * 64 + (lane & 3) * 2;
#pragma unroll
    for (int mt = 0; mt < 2; mt++) {
        int r = rbase + mt * 16;
#pragma unroll
        for (int nt = 0; nt < 8; nt++) {
            int cc = cbase + nt * 8;
            *(float2*)(Cout + (size_t)r * CCLS + cc) =
                make_float2(acc[mt][nt][0], acc[mt][nt][1]);
            *(float2*)(Cout + (size_t)(r + 8) * CCLS + cc) =
                make_float2(acc[mt][nt][2], acc[mt][nt][3]);
        }
    }
}

// ---------------- host launcher ----------------
extern "C" void kernel_launch(void* const* d_in, const int* in_sizes, int n_in,
                              void* d_out, int out_size)
{
    const float* feats  = (const float*)d_in[0];
    const float* protos = (const float*)d_in[1];
    const void*  labels = d_in[2];
    float* out = (float*)d_out;

    static bool attr_set = false;
    if (!attr_set) {
        cudaFuncSetAttribute(gemm_kernel,
                             cudaFuncAttributeMaxDynamicSharedMemorySize, SMEM_GEMM);
        attr_set = true;
    }

    detect_labels_kernel<<<1, 256>>>((const unsigned int*)labels);
    zero_kernel<<<(CCLS * DDIM + 255) / 256, 256>>>();
    norm_scatter_kernel<<<(NROWS * 32 + 255) / 256, 256>>>(feats, labels);
    proto_update_kernel<<<CCLS, 128>>>(protos);

    dim3 grid(CCLS / BN, NROWS / BM);
    gemm_kernel<<<grid, 256, SMEM_GEMM>>>(out);
}

// round 12
// speedup vs baseline: 3.3627x; 2.4839x over previous
#include <cuda_runtime.h>
#include <cuda_bf16.h>
#include <cuda_fp16.h>
#include <cstdint>

#define NROWS 65536
#define CCLS  1024
#define DDIM  512

// ---------------- device scratch (allocation-free rule) ----------------
__device__ __half g_f16[(size_t)NROWS * DDIM];    // 64 MB
__device__ __half g_p16[CCLS * DDIM];             // 1 MB
__device__ float g_sums[CCLS * DDIM];
__device__ float g_cnt[CCLS];
__device__ int   g_lab64;

// ---------------- label dtype sniff ----------------
__global__ void detect_labels_kernel(const unsigned int* __restrict__ lab) {
    __shared__ int any_nz;
    if (threadIdx.x == 0) any_nz = 0;
    __syncthreads();
    int local = 0;
    for (int i = threadIdx.x; i < 8192; i += blockDim.x)
        if (lab[2 * i + 1] != 0u) local = 1;
    if (local) any_nz = 1;
    __syncthreads();
    if (threadIdx.x == 0) g_lab64 = any_nz ? 0 : 1;
}

__global__ void zero_kernel() {
    int i = blockIdx.x * blockDim.x + threadIdx.x;
    if (i < CCLS * DDIM) g_sums[i] = 0.0f;
    if (i < CCLS)        g_cnt[i]  = 0.0f;
}

// ---------------- normalize + scatter + fp16 store ----------------
__global__ __launch_bounds__(256) void norm_scatter_kernel(
    const float* __restrict__ feats, const void* __restrict__ labels)
{
    int row  = (blockIdx.x * blockDim.x + threadIdx.x) >> 5;
    int lane = threadIdx.x & 31;
    if (row >= NROWS) return;

    const float4* src = (const float4*)(feats + (size_t)row * DDIM);
    float4 v[4];
    float ss = 0.0f;
#pragma unroll
    for (int j = 0; j < 4; j++) {
        v[j] = src[lane + 32 * j];
        ss += v[j].x * v[j].x + v[j].y * v[j].y + v[j].z * v[j].z + v[j].w * v[j].w;
    }
#pragma unroll
    for (int o = 16; o; o >>= 1) ss += __shfl_xor_sync(0xFFFFFFFFu, ss, o);
    float inv = 1.0f / fmaxf(sqrtf(ss), 1e-12f);

    int lab;
    if (g_lab64) lab = (int)((const long long*)labels)[row];
    else         lab = ((const int*)labels)[row];

    float* sumrow = g_sums + (size_t)lab * DDIM;
    __half* frow = g_f16 + (size_t)row * DDIM;

#pragma unroll
    for (int j = 0; j < 4; j++) {
        float4 w = make_float4(v[j].x * inv, v[j].y * inv, v[j].z * inv, v[j].w * inv);
        int base = (lane + 32 * j) * 4;
        asm volatile("red.global.add.v4.f32 [%0], {%1,%2,%3,%4};"
                     :: "l"(sumrow + base), "f"(w.x), "f"(w.y), "f"(w.z), "f"(w.w) : "memory");
        __half2 h0 = __floats2half2_rn(w.x, w.y);
        __half2 h1 = __floats2half2_rn(w.z, w.w);
        uint2 hv;
        hv.x = *(unsigned*)&h0; hv.y = *(unsigned*)&h1;
        *(uint2*)(frow + base) = hv;
    }
    if (lane == 0) atomicAdd(&g_cnt[lab], 1.0f);
}

// ---------------- prototype EMA update + renorm + fp16 store ----------------
__global__ __launch_bounds__(128) void proto_update_kernel(
    const float* __restrict__ protos)
{
    int c = blockIdx.x;
    int t = threadIdx.x;
    float cnt = g_cnt[c];

    float4 pv = ((const float4*)(protos + (size_t)c * DDIM))[t];
    float4 sv = ((const float4*)(g_sums + (size_t)c * DDIM))[t];

    float ic = 1.0f / fmaxf(cnt, 1.0f);
    float4 e = make_float4(0.9f * pv.x + 0.1f * sv.x * ic,
                           0.9f * pv.y + 0.1f * sv.y * ic,
                           0.9f * pv.z + 0.1f * sv.z * ic,
                           0.9f * pv.w + 0.1f * sv.w * ic);

    float ss = e.x * e.x + e.y * e.y + e.z * e.z + e.w * e.w;
#pragma unroll
    for (int o = 16; o; o >>= 1) ss += __shfl_xor_sync(0xFFFFFFFFu, ss, o);
    __shared__ float red[4];
    if ((t & 31) == 0) red[t >> 5] = ss;
    __syncthreads();
    float tot = red[0] + red[1] + red[2] + red[3];
    float inv = 1.0f / fmaxf(sqrtf(tot), 1e-12f);

    float4 out;
    if (cnt > 0.0f)
        out = make_float4(e.x * inv, e.y * inv, e.z * inv, e.w * inv);
    else
        out = pv;

    int base = t * 4;
    __half2 h0 = __floats2half2_rn(out.x, out.y);
    __half2 h1 = __floats2half2_rn(out.z, out.w);
    uint2 hv;
    hv.x = *(unsigned*)&h0; hv.y = *(unsigned*)&h1;
    *(uint2*)(g_p16 + (size_t)c * DDIM + base) = hv;
}

// ---------------- single fp16 GEMM via ldmatrix + mma.sync ----------------
// C[N,C] = f16(f) * f16(P)^T, fp32 accumulate
#define BM 128
#define BN 128
#define BK 32
#define NCHUNKS (DDIM / BK)       // 16
#define STAGES 5
#define PRO 4
#define WG  3
#define LDS_EL 40                  // smem row stride in fp16 elems (80 B)
#define TILE_BYTES (128 * LDS_EL * 2)   // 10240
#define OFF_A 0
#define OFF_B TILE_BYTES
#define STAGE_BYTES (2 * TILE_BYTES)    // 20480
#define SMEM_GEMM (STAGES * STAGE_BYTES) // 102400

__device__ __forceinline__ uint32_t smem_u32(const void* p) {
    uint32_t a;
    asm("{ .reg .u64 t; cvta.to.shared.u64 t, %1; cvt.u32.u64 %0, t; }" : "=r"(a) : "l"(p));
    return a;
}
__device__ __forceinline__ void cp16(uint32_t sm, const void* gm) {
    asm volatile("cp.async.cg.shared.global [%0], [%1], 16;" :: "r"(sm), "l"(gm));
}
__device__ __forceinline__ void ldsm_x4(uint32_t* r, uint32_t a) {
    asm volatile("ldmatrix.sync.aligned.m8n8.x4.shared.b16 {%0,%1,%2,%3}, [%4];"
                 : "=r"(r[0]), "=r"(r[1]), "=r"(r[2]), "=r"(r[3]) : "r"(a));
}
__device__ __forceinline__ void mma16816(float* d, const uint32_t* a, const uint32_t* b) {
    asm volatile("mma.sync.aligned.m16n8k16.row.col.f32.f16.f16.f32 "
                 "{%0,%1,%2,%3}, {%4,%5,%6,%7}, {%8,%9}, {%0,%1,%2,%3};"
                 : "+f"(d[0]), "+f"(d[1]), "+f"(d[2]), "+f"(d[3])
                 : "r"(a[0]), "r"(a[1]), "r"(a[2]), "r"(a[3]), "r"(b[0]), "r"(b[1]));
}

__global__ __launch_bounds__(256, 1) void gemm_kernel(float* __restrict__ Cout)
{
    extern __shared__ char smem[];
    const uint32_t sb = smem_u32(smem);
    const int tid  = threadIdx.x;
    const int lane = tid & 31;
    const int wid  = tid >> 5;
    const int mwarp = wid >> 1;          // 0..3
    const int nwarp = wid & 1;           // 0..1
    const int m0 = blockIdx.y * BM;
    const int n0 = blockIdx.x * BN;

    const __half* srcA = g_f16 + (size_t)m0 * DDIM;
    const __half* srcB = g_p16 + (size_t)n0 * DDIM;

    const int r0c = tid >> 2, kc0 = tid & 3;

    float acc[2][8][4];
#pragma unroll
    for (int mt = 0; mt < 2; mt++)
#pragma unroll
        for (int nt = 0; nt < 8; nt++)
#pragma unroll
            for (int q = 0; q < 4; q++) acc[mt][nt][q] = 0.0f;

    // ---- prologue: fill PRO stages ----
#pragma unroll
    for (int s = 0; s < PRO; s++) {
        const int k0 = s * BK;
        const uint32_t stb = sb + s * STAGE_BYTES;
#pragma unroll
        for (int i = 0; i < 2; i++) {
            int row = r0c + i * 64;
            cp16(stb + OFF_A + row * (LDS_EL * 2) + kc0 * 16,
                 srcA + (size_t)row * DDIM + k0 + kc0 * 8);
            cp16(stb + OFF_B + row * (LDS_EL * 2) + kc0 * 16,
                 srcB + (size_t)row * DDIM + k0 + kc0 * 8);
        }
        asm volatile("cp.async.commit_group;" ::: "memory");
    }

    // ldmatrix lane addressing (both operands [row][k], k contiguous -> non-trans)
    const int a_lr = lane & 15, a_lc = lane >> 4;
    const int b_q = lane >> 3;
    const int b_n = ((b_q >> 1) << 3) + (lane & 7);
    const int b_k8 = (b_q & 1) << 3;

    for (int c = 0; c < NCHUNKS; c++) {
        asm volatile("cp.async.wait_group %0;" :: "n"(WG) : "memory");
        __syncthreads();

        // produce chunk c+PRO
        {
            const int cn = c + PRO;
            if (cn < NCHUNKS) {
                const int k0 = cn * BK;
                const uint32_t stb = sb + (cn % STAGES) * STAGE_BYTES;
#pragma unroll
                for (int i = 0; i < 2; i++) {
                    int row = r0c + i * 64;
                    cp16(stb + OFF_A + row * (LDS_EL * 2) + kc0 * 16,
                         srcA + (size_t)row * DDIM + k0 + kc0 * 8);
                    cp16(stb + OFF_B + row * (LDS_EL * 2) + kc0 * 16,
                         srcB + (size_t)row * DDIM + k0 + kc0 * 8);
                }
            }
            asm volatile("cp.async.commit_group;" ::: "memory");  // ALWAYS commit
        }

        const uint32_t stb = sb + (c % STAGES) * STAGE_BYTES;
#pragma unroll
        for (int kk = 0; kk < BK; kk += 16) {
            uint32_t a[2][4], b[8][2];
#pragma unroll
            for (int mt = 0; mt < 2; mt++) {
                uint32_t ab = stb + OFF_A + (mwarp * 32 + mt * 16 + a_lr) * (LDS_EL * 2)
                                   + (kk + a_lc * 8) * 2;
                ldsm_x4(a[mt], ab);
            }
#pragma unroll
            for (int np = 0; np < 4; np++) {
                uint32_t bb = stb + OFF_B + (nwarp * 64 + np * 16 + b_n) * (LDS_EL * 2)
                                   + (kk + b_k8) * 2;
                uint32_t r[4];
                ldsm_x4(r, bb);
                b[2 * np][0] = r[0]; b[2 * np][1] = r[1];
                b[2 * np + 1][0] = r[2]; b[2 * np + 1][1] = r[3];
            }
#pragma unroll
            for (int mt = 0; mt < 2; mt++)
#pragma unroll
                for (int nt = 0; nt < 8; nt++)
                    mma16816(acc[mt][nt], a[mt], b[nt]);
        }
    }

    // ---- epilogue: direct fp32 stores ----
    const int rbase = m0 + mwarp * 32 + (lane >> 2);
    const int cbase = n0 + nwarp * 64 + (lane & 3) * 2;
#pragma unroll
    for (int mt = 0; mt < 2; mt++) {
        int r = rbase + mt * 16;
#pragma unroll
        for (int nt = 0; nt < 8; nt++) {
            int cc = cbase + nt * 8;
            *(float2*)(Cout + (size_t)r * CCLS + cc) =
                make_float2(acc[mt][nt][0], acc[mt][nt][1]);
            *(float2*)(Cout + (size_t)(r + 8) * CCLS + cc) =
                make_float2(acc[mt][nt][2], acc[mt][nt][3]);
        }
    }
}

// ---------------- host launcher ----------------
extern "C" void kernel_launch(void* const* d_in, const int* in_sizes, int n_in,
                              void* d_out, int out_size)
{
    const float* feats  = (const float*)d_in[0];
    const float* protos = (const float*)d_in[1];
    const void*  labels = d_in[2];
    float* out = (float*)d_out;

    static bool attr_set = false;
    if (!attr_set) {
        cudaFuncSetAttribute(gemm_kernel,
                             cudaFuncAttributeMaxDynamicSharedMemorySize, SMEM_GEMM);
        attr_set = true;
    }

    detect_labels_kernel<<<1, 256>>>((const unsigned int*)labels);
    zero_kernel<<<(CCLS * DDIM + 255) / 256, 256>>>();
    norm_scatter_kernel<<<(NROWS * 32 + 255) / 256, 256>>>(feats, labels);
    proto_update_kernel<<<CCLS, 128>>>(protos);

    dim3 grid(CCLS / BN, NROWS / BM);
    gemm_kernel<<<grid, 256, SMEM_GEMM>>>(out);
}

// round 13
// speedup vs baseline: 3.6019x; 1.0711x over previous
#include <cuda_runtime.h>
#include <cuda_bf16.h>
#include <cuda_fp16.h>
#include <cstdint>

#define NROWS 65536
#define CCLS  1024
#define DDIM  512

// ---------------- device scratch (allocation-free rule) ----------------
__device__ __half g_f16[(size_t)NROWS * DDIM];    // 64 MB
__device__ __half g_p16[CCLS * DDIM];             // 1 MB
__device__ float g_sums[CCLS * DDIM];
__device__ float g_cnt[CCLS];
__device__ int   g_lab64;

// ---------------- label dtype sniff ----------------
__global__ void detect_labels_kernel(const unsigned int* __restrict__ lab) {
    __shared__ int any_nz;
    if (threadIdx.x == 0) any_nz = 0;
    __syncthreads();
    int local = 0;
    for (int i = threadIdx.x; i < 8192; i += blockDim.x)
        if (lab[2 * i + 1] != 0u) local = 1;
    if (local) any_nz = 1;
    __syncthreads();
    if (threadIdx.x == 0) g_lab64 = any_nz ? 0 : 1;
}

__global__ void zero_kernel() {
    int i = blockIdx.x * blockDim.x + threadIdx.x;
    if (i < CCLS * DDIM) g_sums[i] = 0.0f;
    if (i < CCLS)        g_cnt[i]  = 0.0f;
}

// ---------------- normalize + scatter + fp16 store ----------------
__global__ __launch_bounds__(256) void norm_scatter_kernel(
    const float* __restrict__ feats, const void* __restrict__ labels)
{
    int row  = (blockIdx.x * blockDim.x + threadIdx.x) >> 5;
    int lane = threadIdx.x & 31;
    if (row >= NROWS) return;

    const float4* src = (const float4*)(feats + (size_t)row * DDIM);
    float4 v[4];
    float ss = 0.0f;
#pragma unroll
    for (int j = 0; j < 4; j++) {
        v[j] = src[lane + 32 * j];
        ss += v[j].x * v[j].x + v[j].y * v[j].y + v[j].z * v[j].z + v[j].w * v[j].w;
    }
#pragma unroll
    for (int o = 16; o; o >>= 1) ss += __shfl_xor_sync(0xFFFFFFFFu, ss, o);
    float inv = 1.0f / fmaxf(sqrtf(ss), 1e-12f);

    int lab;
    if (g_lab64) lab = (int)((const long long*)labels)[row];
    else         lab = ((const int*)labels)[row];

    float* sumrow = g_sums + (size_t)lab * DDIM;
    __half* frow = g_f16 + (size_t)row * DDIM;

#pragma unroll
    for (int j = 0; j < 4; j++) {
        float4 w = make_float4(v[j].x * inv, v[j].y * inv, v[j].z * inv, v[j].w * inv);
        int base = (lane + 32 * j) * 4;
        asm volatile("red.global.add.v4.f32 [%0], {%1,%2,%3,%4};"
                     :: "l"(sumrow + base), "f"(w.x), "f"(w.y), "f"(w.z), "f"(w.w) : "memory");
        __half2 h0 = __floats2half2_rn(w.x, w.y);
        __half2 h1 = __floats2half2_rn(w.z, w.w);
        uint2 hv;
        hv.x = *(unsigned*)&h0; hv.y = *(unsigned*)&h1;
        *(uint2*)(frow + base) = hv;
    }
    if (lane == 0) atomicAdd(&g_cnt[lab], 1.0f);
}

// ---------------- prototype EMA update + renorm + fp16 store ----------------
__global__ __launch_bounds__(128) void proto_update_kernel(
    const float* __restrict__ protos)
{
    int c = blockIdx.x;
    int t = threadIdx.x;
    float cnt = g_cnt[c];

    float4 pv = ((const float4*)(protos + (size_t)c * DDIM))[t];
    float4 sv = ((const float4*)(g_sums + (size_t)c * DDIM))[t];

    float ic = 1.0f / fmaxf(cnt, 1.0f);
    float4 e = make_float4(0.9f * pv.x + 0.1f * sv.x * ic,
                           0.9f * pv.y + 0.1f * sv.y * ic,
                           0.9f * pv.z + 0.1f * sv.z * ic,
                           0.9f * pv.w + 0.1f * sv.w * ic);

    float ss = e.x * e.x + e.y * e.y + e.z * e.z + e.w * e.w;
#pragma unroll
    for (int o = 16; o; o >>= 1) ss += __shfl_xor_sync(0xFFFFFFFFu, ss, o);
    __shared__ float red[4];
    if ((t & 31) == 0) red[t >> 5] = ss;
    __syncthreads();
    float tot = red[0] + red[1] + red[2] + red[3];
    float inv = 1.0f / fmaxf(sqrtf(tot), 1e-12f);

    float4 out;
    if (cnt > 0.0f)
        out = make_float4(e.x * inv, e.y * inv, e.z * inv, e.w * inv);
    else
        out = pv;

    int base = t * 4;
    __half2 h0 = __floats2half2_rn(out.x, out.y);
    __half2 h1 = __floats2half2_rn(out.z, out.w);
    uint2 hv;
    hv.x = *(unsigned*)&h0; hv.y = *(unsigned*)&h1;
    *(uint2*)(g_p16 + (size_t)c * DDIM + base) = hv;
}

// ---------------- single fp16 GEMM, BM=128 x BN=256, 512 threads ----------------
#define BM 128
#define BN 256
#define BK 32
#define NCHUNKS (DDIM / BK)       // 16
#define STAGES 5
#define PRO 4
#define WG  3
#define LDS_EL 40                  // smem row stride in fp16 elems (80 B)
#define OFF_A 0
#define OFF_B (BM * LDS_EL * 2)              // 10240 (A: 128 rows)
#define STAGE_BYTES ((BM + BN) * LDS_EL * 2) // 30720 (A+B: 384 rows)
#define SMEM_GEMM (STAGES * STAGE_BYTES)     // 153600
#define NTHREADS 512

__device__ __forceinline__ uint32_t smem_u32(const void* p) {
    uint32_t a;
    asm("{ .reg .u64 t; cvta.to.shared.u64 t, %1; cvt.u32.u64 %0, t; }" : "=r"(a) : "l"(p));
    return a;
}
__device__ __forceinline__ void cp16(uint32_t sm, const void* gm) {
    asm volatile("cp.async.cg.shared.global [%0], [%1], 16;" :: "r"(sm), "l"(gm));
}
__device__ __forceinline__ void ldsm_x4(uint32_t* r, uint32_t a) {
    asm volatile("ldmatrix.sync.aligned.m8n8.x4.shared.b16 {%0,%1,%2,%3}, [%4];"
                 : "=r"(r[0]), "=r"(r[1]), "=r"(r[2]), "=r"(r[3]) : "r"(a));
}
__device__ __forceinline__ void mma16816(float* d, const uint32_t* a, const uint32_t* b) {
    asm volatile("mma.sync.aligned.m16n8k16.row.col.f32.f16.f16.f32 "
                 "{%0,%1,%2,%3}, {%4,%5,%6,%7}, {%8,%9}, {%0,%1,%2,%3};"
                 : "+f"(d[0]), "+f"(d[1]), "+f"(d[2]), "+f"(d[3])
                 : "r"(a[0]), "r"(a[1]), "r"(a[2]), "r"(a[3]), "r"(b[0]), "r"(b[1]));
}

// load one 32-k chunk (A: 128 rows, B: 256 rows) into a stage
__device__ __forceinline__ void load_chunk(uint32_t stb, const __half* srcA,
                                           const __half* srcB, int k0, int tid) {
#pragma unroll
    for (int j = 0; j < 3; j++) {
        int idx = tid + j * NTHREADS;        // 0..1535
        int row = idx >> 2;                  // 0..383
        int kc  = idx & 3;
        if (row < BM) {
            cp16(stb + OFF_A + row * (LDS_EL * 2) + kc * 16,
                 srcA + (size_t)row * DDIM + k0 + kc * 8);
        } else {
            int br = row - BM;               // 0..255
            cp16(stb + OFF_B + br * (LDS_EL * 2) + kc * 16,
                 srcB + (size_t)br * DDIM + k0 + kc * 8);
        }
    }
}

__global__ __launch_bounds__(NTHREADS, 1) void gemm_kernel(float* __restrict__ Cout)
{
    extern __shared__ char smem[];
    const uint32_t sb = smem_u32(smem);
    const int tid  = threadIdx.x;
    const int lane = tid & 31;
    const int wid  = tid >> 5;
    const int mwarp = wid >> 2;          // 0..3 (x32 rows)
    const int nwarp = wid & 3;           // 0..3 (x64 cols)
    const int m0 = blockIdx.y * BM;
    const int n0 = blockIdx.x * BN;

    const __half* srcA = g_f16 + (size_t)m0 * DDIM;
    const __half* srcB = g_p16 + (size_t)n0 * DDIM;

    float acc[2][8][4];
#pragma unroll
    for (int mt = 0; mt < 2; mt++)
#pragma unroll
        for (int nt = 0; nt < 8; nt++)
#pragma unroll
            for (int q = 0; q < 4; q++) acc[mt][nt][q] = 0.0f;

    // ---- prologue: fill PRO stages ----
#pragma unroll
    for (int s = 0; s < PRO; s++) {
        load_chunk(sb + s * STAGE_BYTES, srcA, srcB, s * BK, tid);
        asm volatile("cp.async.commit_group;" ::: "memory");
    }

    // ldmatrix lane addressing (both operands [row][k], k contiguous -> non-trans)
    const int a_lr = lane & 15, a_lc = lane >> 4;
    const int b_q = lane >> 3;
    const int b_n = ((b_q >> 1) << 3) + (lane & 7);
    const int b_k8 = (b_q & 1) << 3;

    for (int c = 0; c < NCHUNKS; c++) {
        asm volatile("cp.async.wait_group %0;" :: "n"(WG) : "memory");
        __syncthreads();

        // produce chunk c+PRO
        {
            const int cn = c + PRO;
            if (cn < NCHUNKS) {
                load_chunk(sb + (cn % STAGES) * STAGE_BYTES, srcA, srcB, cn * BK, tid);
            }
            asm volatile("cp.async.commit_group;" ::: "memory");  // ALWAYS commit
        }

        const uint32_t stb = sb + (c % STAGES) * STAGE_BYTES;
#pragma unroll
        for (int kk = 0; kk < BK; kk += 16) {
            uint32_t a[2][4], b[8][2];
#pragma unroll
            for (int mt = 0; mt < 2; mt++) {
                uint32_t ab = stb + OFF_A + (mwarp * 32 + mt * 16 + a_lr) * (LDS_EL * 2)
                                   + (kk + a_lc * 8) * 2;
                ldsm_x4(a[mt], ab);
            }
#pragma unroll
            for (int np = 0; np < 4; np++) {
                uint32_t bb = stb + OFF_B + (nwarp * 64 + np * 16 + b_n) * (LDS_EL * 2)
                                   + (kk + b_k8) * 2;
                uint32_t r[4];
                ldsm_x4(r, bb);
                b[2 * np][0] = r[0]; b[2 * np][1] = r[1];
                b[2 * np + 1][0] = r[2]; b[2 * np + 1][1] = r[3];
            }
#pragma unroll
            for (int mt = 0; mt < 2; mt++)
#pragma unroll
                for (int nt = 0; nt < 8; nt++)
                    mma16816(acc[mt][nt], a[mt], b[nt]);
        }
    }

    // ---- epilogue: direct fp32 stores ----
    const int rbase = m0 + mwarp * 32 + (lane >> 2);
    const int cbase = n0 + nwarp * 64 + (lane & 3) * 2;
#pragma unroll
    for (int mt = 0; mt < 2; mt++) {
        int r = rbase + mt * 16;
#pragma unroll
        for (int nt = 0; nt < 8; nt++) {
            int cc = cbase + nt * 8;
            *(float2*)(Cout + (size_t)r * CCLS + cc) =
                make_float2(acc[mt][nt][0], acc[mt][nt][1]);
            *(float2*)(Cout + (size_t)(r + 8) * CCLS + cc) =
                make_float2(acc[mt][nt][2], acc[mt][nt][3]);
        }
    }
}

// ---------------- host launcher ----------------
extern "C" void kernel_launch(void* const* d_in, const int* in_sizes, int n_in,
                              void* d_out, int out_size)
{
    const float* feats  = (const float*)d_in[0];
    const float* protos = (const float*)d_in[1];
    const void*  labels = d_in[2];
    float* out = (float*)d_out;

    static bool attr_set = false;
    if (!attr_set) {
        cudaFuncSetAttribute(gemm_kernel,
                             cudaFuncAttributeMaxDynamicSharedMemorySize, SMEM_GEMM);
        attr_set = true;
    }

    detect_labels_kernel<<<1, 256>>>((const unsigned int*)labels);
    zero_kernel<<<(CCLS * DDIM + 255) / 256, 256>>>();
    norm_scatter_kernel<<<(NROWS * 32 + 255) / 256, 256>>>(feats, labels);
    proto_update_kernel<<<CCLS, 128>>>(protos);

    dim3 grid(CCLS / BN, NROWS / BM);
    gemm_kernel<<<grid, NTHREADS, SMEM_GEMM>>>(out);
}